// round 4
// baseline (speedup 1.0000x reference)
#include <cuda_runtime.h>
#include <math.h>

#define B  32
#define S  196
#define T  64
#define H  1024
#define V  32000
#define G4 4096

// ---------------- scratch (static device memory; no allocs) ----------------
__device__ float g_xW[(size_t)T * B * G4];        // [t][b][4H]  emb@W_ih_x.T + b_ih + b_hh
__device__ float g_Hbuf[(size_t)(T + 1) * B * H]; // h states; slot 0 = zeros, slot t+1 = h after step t
__device__ float g_cbuf[2 * B * H];               // c double buffer
__device__ float g_q[B * H];
__device__ float g_scores[B * S];
__device__ float g_ctx[B * H];

// ---------------- init ----------------
__global__ void k_zero() {
    int i = blockIdx.x * blockDim.x + threadIdx.x;
    if (i < B * H) {
        g_Hbuf[i] = 0.f;      // h_0 = 0
        g_cbuf[i] = 0.f;      // c_0 = 0 (buffer parity 0 is read at t=0)
    }
}

// ---------------- big SGEMM: C[M=2048, N] = A[2048,1024] @ Bw[N,1024]^T ----------------
// Software-pipelined: next k-tile is prefetched into registers during compute.
// MODE 0: A rows gathered from emb_table via captions (row r=(t*32+b) -> token captions[b*T+t]);
//         writes g_xW[r*4096+n] + b_ih[n] + b_hh[n]
// MODE 1: A = g_Hbuf + B*H (h_1..h_64); writes out[b*T*V + t*V + n] + b_out[n]
template <int MODE>
__global__ __launch_bounds__(256, 2) void sgemm128(
    const float* __restrict__ Aext, const float* __restrict__ Bw,
    const float* __restrict__ bias1, const float* __restrict__ bias2,
    const int* __restrict__ caps, float* __restrict__ Cout,
    int N, int ldb, int boff)
{
    __shared__ float As[8][128];
    __shared__ float Bs[8][128];

    const int tid = threadIdx.x;
    const int bx = blockIdx.x, by = blockIdx.y;
    const int tx = tid & 15, ty = tid >> 4;

    const int ldRow = tid >> 1;          // 0..127
    const int ldCol = (tid & 1) * 4;     // 0 or 4

    // A global pointer for this thread's load slice
    const int gRowA = by * 128 + ldRow;
    const float* aptr;
    if (MODE == 0) {
        int b = gRowA & 31, t = gRowA >> 5;
        int token = caps[b * T + t];
        aptr = Aext + (size_t)token * H + ldCol;
    } else {
        aptr = g_Hbuf + (size_t)B * H + (size_t)gRowA * H + ldCol;
    }
    const int gRowB = bx * 128 + ldRow;
    const float* bptr = Bw + (size_t)gRowB * ldb + boff + ldCol;

    float acc[8][8];
#pragma unroll
    for (int i = 0; i < 8; i++)
#pragma unroll
        for (int j = 0; j < 8; j++) acc[i][j] = 0.f;

    // Prologue: fetch first tile into registers
    float4 av = *(const float4*)(aptr);
    float4 bv = *(const float4*)(bptr);

    for (int k0 = 0; k0 < H; k0 += 8) {
        As[ldCol + 0][ldRow] = av.x; As[ldCol + 1][ldRow] = av.y;
        As[ldCol + 2][ldRow] = av.z; As[ldCol + 3][ldRow] = av.w;
        Bs[ldCol + 0][ldRow] = bv.x; Bs[ldCol + 1][ldRow] = bv.y;
        Bs[ldCol + 2][ldRow] = bv.z; Bs[ldCol + 3][ldRow] = bv.w;
        __syncthreads();

        // Prefetch next k-tile while computing this one (hides LDG latency)
        if (k0 + 8 < H) {
            av = *(const float4*)(aptr + k0 + 8);
            bv = *(const float4*)(bptr + k0 + 8);
        }

#pragma unroll
        for (int kk = 0; kk < 8; kk++) {
            float4 a0 = *(const float4*)&As[kk][ty * 8];
            float4 a1 = *(const float4*)&As[kk][ty * 8 + 4];
            float4 b0 = *(const float4*)&Bs[kk][tx * 8];
            float4 b1 = *(const float4*)&Bs[kk][tx * 8 + 4];
            float a[8] = {a0.x, a0.y, a0.z, a0.w, a1.x, a1.y, a1.z, a1.w};
            float bb[8] = {b0.x, b0.y, b0.z, b0.w, b1.x, b1.y, b1.z, b1.w};
#pragma unroll
            for (int i = 0; i < 8; i++)
#pragma unroll
                for (int j = 0; j < 8; j++) acc[i][j] += a[i] * bb[j];
        }
        __syncthreads();
    }

#pragma unroll
    for (int i = 0; i < 8; i++) {
        int m = by * 128 + ty * 8 + i;
        int t = m >> 5, b = m & 31;
#pragma unroll
        for (int j = 0; j < 8; j += 4) {
            int n = bx * 128 + tx * 8 + j;
            float4 o;
            if (MODE == 0) {
                o.x = acc[i][j + 0] + bias1[n + 0] + bias2[n + 0];
                o.y = acc[i][j + 1] + bias1[n + 1] + bias2[n + 1];
                o.z = acc[i][j + 2] + bias1[n + 2] + bias2[n + 2];
                o.w = acc[i][j + 3] + bias1[n + 3] + bias2[n + 3];
                *(float4*)&g_xW[(size_t)m * G4 + n] = o;
            } else {
                o.x = acc[i][j + 0] + bias1[n + 0];
                o.y = acc[i][j + 1] + bias1[n + 1];
                o.z = acc[i][j + 2] + bias1[n + 2];
                o.w = acc[i][j + 3] + bias1[n + 3];
                size_t off = (size_t)b * ((size_t)T * V) + (size_t)t * V + n;
                *(float4*)&Cout[off] = o;
            }
        }
    }
}

// ---------------- q = h @ attn_W^T  (M=32, N=1024, K=1024) ----------------
__global__ __launch_bounds__(256) void k_q(const float* __restrict__ attnW, int t)
{
    __shared__ float sH[32][68];
    __shared__ float sW[8][68];
    const float* hbase = g_Hbuf + (size_t)t * B * H;
    const int tid = threadIdx.x;
    const int n0 = blockIdx.x * 8;           // 128 blocks
    const int b = tid >> 3, ji = tid & 7;
    float acc = 0.f;

    for (int k0 = 0; k0 < H; k0 += 64) {
        __syncthreads();
        {
            int row = tid >> 3;
            int kk = (tid & 7) * 8;
            const float* p = hbase + row * H + k0 + kk;
            *(float4*)&sH[row][kk] = *(const float4*)p;
            *(float4*)&sH[row][kk + 4] = *(const float4*)(p + 4);
            if (tid < 64) {
                int wr = tid >> 3;
                int kw = (tid & 7) * 8;
                const float* wp = attnW + (size_t)(n0 + wr) * H + k0 + kw;
                *(float4*)&sW[wr][kw] = *(const float4*)wp;
                *(float4*)&sW[wr][kw + 4] = *(const float4*)(wp + 4);
            }
        }
        __syncthreads();
#pragma unroll
        for (int kk = 0; kk < 64; kk += 4) {
            float4 a = *(const float4*)&sH[b][kk];
            float4 w = *(const float4*)&sW[ji][kk];
            acc += a.x * w.x + a.y * w.y + a.z * w.z + a.w * w.w;
        }
    }
    g_q[b * H + n0 + ji] = acc;
}

// ---------------- scores[b][s] = q[b] . memory[b][s] ----------------
__global__ __launch_bounds__(256) void k_scores(const float* __restrict__ mem)
{
    __shared__ float sQ[H];
    const int sc = blockIdx.x;   // 0..6 (28 s each)
    const int b = blockIdx.y;
    const int tid = threadIdx.x;
    for (int i = tid; i < H; i += 256) sQ[i] = g_q[b * H + i];
    __syncthreads();
    const int warp = tid >> 5, lane = tid & 31;
    for (int si = warp; si < 28; si += 8) {
        int s = sc * 28 + si;
        const float* mrow = mem + ((size_t)b * S + s) * H;
        float acc = 0.f;
#pragma unroll
        for (int i = 0; i < 8; i++) {
            int k = i * 128 + lane * 4;
            float4 m4 = *(const float4*)(mrow + k);
            float4 q4 = *(const float4*)&sQ[k];
            acc += m4.x * q4.x + m4.y * q4.y + m4.z * q4.z + m4.w * q4.w;
        }
#pragma unroll
        for (int o = 16; o > 0; o >>= 1) acc += __shfl_down_sync(0xffffffffu, acc, o);
        if (lane == 0) g_scores[b * S + s] = acc;
    }
}

// ---------------- softmax + ctx[b][h] = sum_s w[s]*memory[b][s][h] ----------------
__global__ __launch_bounds__(256) void k_ctxsm(const float* __restrict__ mem)
{
    __shared__ float sw_[S];
    __shared__ float red[8];
    const int b = blockIdx.y;
    const int tid = threadIdx.x;
    const int warp = tid >> 5, lane = tid & 31;

    float v = (tid < S) ? g_scores[b * S + tid] : -1e30f;
    float m = v;
#pragma unroll
    for (int o = 16; o > 0; o >>= 1) m = fmaxf(m, __shfl_xor_sync(0xffffffffu, m, o));
    if (lane == 0) red[warp] = m;
    __syncthreads();
    float bm = red[0];
#pragma unroll
    for (int w = 1; w < 8; w++) bm = fmaxf(bm, red[w]);
    float e = (tid < S) ? expf(v - bm) : 0.f;
    __syncthreads();
    float sacc = e;
#pragma unroll
    for (int o = 16; o > 0; o >>= 1) sacc += __shfl_xor_sync(0xffffffffu, sacc, o);
    if (lane == 0) red[warp] = sacc;
    __syncthreads();
    float total = 0.f;
#pragma unroll
    for (int w = 0; w < 8; w++) total += red[w];
    if (tid < S) sw_[tid] = e / total;
    __syncthreads();

    int h = blockIdx.x * 256 + tid;       // gridDim.x = 4
    const float* mb = mem + (size_t)b * S * H + h;
    float acc = 0.f;
    // 196 = 7 * 28: unroll by 7 to raise MLP (independent strided loads in flight)
#pragma unroll 7
    for (int s2 = 0; s2 < S; s2++) acc += sw_[s2] * mb[(size_t)s2 * H];
    g_ctx[b * H + h] = acc;
}

// ---------------- gates + LSTM pointwise ----------------
// block jt (128 blocks): j in [jt*8, jt*8+8); computes all 4 gates for all 32 b,
// then applies the LSTM cell and writes h -> g_Hbuf[t+1], c -> parity buffer.
__global__ __launch_bounds__(256) void k_gates(const float* __restrict__ W_ih,
                                               const float* __restrict__ W_hh, int t)
{
    __shared__ float sA[32][68];
    __shared__ float sW[32][68];
    const int tid = threadIdx.x;
    const int j0 = blockIdx.x * 8;
    const int b = tid >> 3, ji = tid & 7;
    float acc[4] = {0.f, 0.f, 0.f, 0.f};
    const float* hprev = g_Hbuf + (size_t)t * B * H;

    for (int src = 0; src < 2; src++) {
        const float* Ain = (src == 0) ? g_ctx : hprev;
        const float* Wbase = (src == 0) ? W_ih : W_hh;
        const int ldw = (src == 0) ? 2 * H : H;
        const int off = (src == 0) ? H : 0;
        for (int k0 = 0; k0 < H; k0 += 64) {
            __syncthreads();
            {
                int row = tid >> 3;
                int kk = (tid & 7) * 8;
                const float* p = Ain + row * H + k0 + kk;
                *(float4*)&sA[row][kk] = *(const float4*)p;
                *(float4*)&sA[row][kk + 4] = *(const float4*)(p + 4);
                int n = (row >> 3) * H + j0 + (row & 7);   // gate*H + j
                const float* wp = Wbase + (size_t)n * ldw + off + k0 + kk;
                *(float4*)&sW[row][kk] = *(const float4*)wp;
                *(float4*)&sW[row][kk + 4] = *(const float4*)(wp + 4);
            }
            __syncthreads();
#pragma unroll
            for (int kk = 0; kk < 64; kk += 4) {
                float4 a = *(const float4*)&sA[b][kk];
#pragma unroll
                for (int g = 0; g < 4; g++) {
                    float4 w = *(const float4*)&sW[g * 8 + ji][kk];
                    acc[g] += a.x * w.x + a.y * w.y + a.z * w.z + a.w * w.w;
                }
            }
        }
    }

    const int j = j0 + ji;
    const size_t xbase = ((size_t)t * B + b) * G4 + j;
    float gi = acc[0] + g_xW[xbase];
    float gf = acc[1] + g_xW[xbase + H];
    float gg = acc[2] + g_xW[xbase + 2 * H];
    float go = acc[3] + g_xW[xbase + 3 * H];
    gi = 1.f / (1.f + expf(-gi));
    gf = 1.f / (1.f + expf(-gf));
    gg = tanhf(gg);
    go = 1.f / (1.f + expf(-go));
    float c_old = g_cbuf[(t & 1) * B * H + b * H + j];
    float c_new = gf * c_old + gi * gg;
    float h_new = go * tanhf(c_new);
    g_cbuf[((t + 1) & 1) * B * H + b * H + j] = c_new;
    g_Hbuf[(size_t)(t + 1) * B * H + b * H + j] = h_new;
}

// ---------------- tail: final h, c ----------------
__global__ void k_tail(float* __restrict__ out)
{
    int i = blockIdx.x * blockDim.x + threadIdx.x;
    if (i < B * H) {
        out[(size_t)B * T * V + i] = g_Hbuf[(size_t)T * B * H + i];   // h_64
        out[(size_t)B * T * V + B * H + i] = g_cbuf[0 * B * H + i];   // c after t=63 (parity 0)
    }
}

// ---------------- launch ----------------
extern "C" void kernel_launch(void* const* d_in, const int* in_sizes, int n_in,
                              void* d_out, int out_size)
{
    const float* memory   = (const float*)d_in[0];
    const int*   captions = (const int*)d_in[1];
    const float* emb      = (const float*)d_in[2];
    const float* attnW    = (const float*)d_in[3];
    const float* W_ih     = (const float*)d_in[4];
    const float* W_hh     = (const float*)d_in[5];
    const float* b_ih     = (const float*)d_in[6];
    const float* b_hh     = (const float*)d_in[7];
    const float* W_out    = (const float*)d_in[8];
    const float* b_out    = (const float*)d_in[9];
    float* out = (float*)d_out;

    k_zero<<<(B * H + 255) / 256, 256>>>();

    // Precompute xW[t][b][4H] = emb_table[captions] @ W_ih[:, :H].T + b_ih + b_hh
    {
        dim3 g(G4 / 128, (T * B) / 128);   // (32, 16)
        sgemm128<0><<<g, 256>>>(emb, W_ih, b_ih, b_hh, captions, nullptr, G4, 2 * H, 0);
    }

    for (int t = 0; t < T; t++) {
        k_q<<<128, 256>>>(attnW, t);
        k_scores<<<dim3(7, B), 256>>>(memory);
        k_ctxsm<<<dim3(4, B), 256>>>(memory);
        k_gates<<<128, 256>>>(W_ih, W_hh, t);
    }

    // logits[b][t][v] = h_{t+1} @ W_out.T + b_out, batched over all 2048 (t,b) rows
    {
        dim3 g(V / 128, (T * B) / 128);    // (250, 16)
        sgemm128<1><<<g, 256>>>(nullptr, W_out, b_out, nullptr, nullptr, out, V, H, 0);
    }

    k_tail<<<(B * H + 255) / 256, 256>>>(out);
}

// round 6
// speedup vs baseline: 1.0214x; 1.0214x over previous
#include <cuda_runtime.h>
#include <cuda_bf16.h>
#include <math.h>
#include <stdint.h>

#define B  32
#define S  196
#define T  64
#define H  1024
#define V  32000
#define G4 4096

// MMA GEMM tiling
#define TM 128
#define TN 128
#define KC 32
#define NKC (H / KC)                 // 32 chunks
#define ROWB 80                      // SMEM row pitch bytes (32 bf16 data + pad) -> conflict-free
#define TILE_SM (128 * ROWB)         // 10240 B per tile
#define BUF_SM (4 * TILE_SM)         // Ah, Al, Bh, Bl
#define SMEM_MMA (2 * BUF_SM)        // 81920 B double-buffered

// ---------------- scratch (static device memory; no allocs) ----------------
__device__ float g_xW[(size_t)T * B * G4];        // [t][b][4H]
__device__ float g_Hbuf[(size_t)(T + 1) * B * H]; // h states; slot t+1 = h after step t
__device__ float g_cbuf[2 * B * H];
__device__ float g_q[B * H];
__device__ float g_ctx[B * H];

// bf16 hi/lo split staging, plain row-major [rows][H]
__device__ __align__(16) unsigned char g_Whi[(size_t)V * H * 2];
__device__ __align__(16) unsigned char g_Wlo[(size_t)V * H * 2];
__device__ __align__(16) unsigned char g_Ahi[(size_t)T * B * H * 2];
__device__ __align__(16) unsigned char g_Alo[(size_t)T * B * H * 2];

__device__ __forceinline__ void split2(float x, unsigned short& hi, unsigned short& lo) {
    __nv_bfloat16 h = __float2bfloat16(x);
    float hf = __bfloat162float(h);
    __nv_bfloat16 l = __float2bfloat16(x - hf);
    hi = *reinterpret_cast<unsigned short*>(&h);
    lo = *reinterpret_cast<unsigned short*>(&l);
}

// ---------------- init ----------------
__global__ void k_zero() {
    int i = blockIdx.x * blockDim.x + threadIdx.x;
    if (i < B * H) { g_Hbuf[i] = 0.f; g_cbuf[i] = 0.f; }
}

// ---------------- convert W_out -> bf16 hi/lo (row-major) ----------------
__global__ void k_convW(const float* __restrict__ W) {
    int n = blockIdx.x;               // 0..V-1
    int k0 = threadIdx.x * 4;         // 0..1020
    float4 w = *(const float4*)(W + (size_t)n * H + k0);
    unsigned short h0, h1, h2, h3, l0, l1, l2, l3;
    split2(w.x, h0, l0); split2(w.y, h1, l1); split2(w.z, h2, l2); split2(w.w, h3, l3);
    uint2 hv = make_uint2((uint32_t)h0 | ((uint32_t)h1 << 16), (uint32_t)h2 | ((uint32_t)h3 << 16));
    uint2 lv = make_uint2((uint32_t)l0 | ((uint32_t)l1 << 16), (uint32_t)l2 | ((uint32_t)l3 << 16));
    *(uint2*)(g_Whi + ((size_t)n * H + k0) * 2) = hv;
    *(uint2*)(g_Wlo + ((size_t)n * H + k0) * 2) = lv;
}

// ---------------- convert h matrix (row m = t*32+b -> h_{t+1}[b]) ----------------
__global__ void k_convA() {
    int m = blockIdx.x;               // 0..2047
    int k0 = threadIdx.x * 4;
    float4 w = *(const float4*)(g_Hbuf + (size_t)(m + B) * H + k0);
    unsigned short h0, h1, h2, h3, l0, l1, l2, l3;
    split2(w.x, h0, l0); split2(w.y, h1, l1); split2(w.z, h2, l2); split2(w.w, h3, l3);
    uint2 hv = make_uint2((uint32_t)h0 | ((uint32_t)h1 << 16), (uint32_t)h2 | ((uint32_t)h3 << 16));
    uint2 lv = make_uint2((uint32_t)l0 | ((uint32_t)l1 << 16), (uint32_t)l2 | ((uint32_t)l3 << 16));
    *(uint2*)(g_Ahi + ((size_t)m * H + k0) * 2) = hv;
    *(uint2*)(g_Alo + ((size_t)m * H + k0) * 2) = lv;
}

// ---------------- mma helpers ----------------
__device__ __forceinline__ void mma16816(float* d, const uint32_t* a, const uint32_t* b) {
    asm volatile(
        "mma.sync.aligned.m16n8k16.row.col.f32.bf16.bf16.f32 "
        "{%0,%1,%2,%3}, {%4,%5,%6,%7}, {%8,%9}, {%0,%1,%2,%3};"
        : "+f"(d[0]), "+f"(d[1]), "+f"(d[2]), "+f"(d[3])
        : "r"(a[0]), "r"(a[1]), "r"(a[2]), "r"(a[3]), "r"(b[0]), "r"(b[1]));
}

__device__ __forceinline__ void cp16(void* dst_smem, const void* src_gmem) {
    uint32_t d;
    asm("{ .reg .u64 t; cvta.to.shared.u64 t, %1; cvt.u32.u64 %0, t; }" : "=r"(d) : "l"(dst_smem));
    asm volatile("cp.async.ca.shared.global [%0], [%1], 16;" :: "r"(d), "l"(src_gmem) : "memory");
}

// ---------------- tensor-core vocab GEMM ----------------
// out[b, t, v] = sum_k h[m,k] * W[v,k] + b_out[v], m = t*32+b
// Split bf16: Ahi*Bhi + Ahi*Blo + Alo*Bhi, fp32 accumulate.
__global__ __launch_bounds__(256) void k_mma2(const float* __restrict__ bout,
                                              float* __restrict__ out) {
    extern __shared__ __align__(16) unsigned char sm[];
    const int tid = threadIdx.x;
    const int wid = tid >> 5, lane = tid & 31;
    const int gid = lane >> 2, tig = lane & 3;
    const int wm = wid >> 2, wn = wid & 3;           // 2 x 4 warp grid
    const int mt = blockIdx.x, nt = blockIdx.y;

    const size_t aRow0 = (size_t)mt * TM;            // global A row base
    const size_t bRow0 = (size_t)nt * TN;            // global W row base

    float acc[4][4][4];
#pragma unroll
    for (int i = 0; i < 4; i++)
#pragma unroll
        for (int j = 0; j < 4; j++)
#pragma unroll
            for (int q = 0; q < 4; q++) acc[i][j][q] = 0.f;

    // cp.async loader: 512 16B-chunks per tile; thread covers idx = tid, tid+256
    auto load_chunk = [&](int kc, int buf) {
        unsigned char* base = sm + buf * BUF_SM;
        const int kOff = kc * KC;                    // bf16 col offset
#pragma unroll
        for (int half = 0; half < 2; half++) {
            int idx = tid + half * 256;              // 0..511
            int row = idx >> 2, quad = idx & 3;
            size_t gA = ((aRow0 + row) * (size_t)H + kOff + quad * 8) * 2;
            size_t gB = ((bRow0 + row) * (size_t)H + kOff + quad * 8) * 2;
            uint32_t so = row * ROWB + quad * 16;
            cp16(base + so,               g_Ahi + gA);
            cp16(base + TILE_SM + so,     g_Alo + gA);
            cp16(base + 2 * TILE_SM + so, g_Whi + gB);
            cp16(base + 3 * TILE_SM + so, g_Wlo + gB);
        }
        asm volatile("cp.async.commit_group;" ::: "memory");
    };

    load_chunk(0, 0);

    for (int kc = 0; kc < NKC; kc++) {
        const int cur = kc & 1;
        if (kc + 1 < NKC) {
            load_chunk(kc + 1, cur ^ 1);
            asm volatile("cp.async.wait_group 1;" ::: "memory");
        } else {
            asm volatile("cp.async.wait_group 0;" ::: "memory");
        }
        __syncthreads();

        const unsigned char* base = sm + cur * BUF_SM;
#pragma unroll
        for (int ks = 0; ks < 2; ks++) {
            const int kcol = ks * 16;                 // bf16 col within chunk
            uint32_t ah[4][4], al[4][4], bh[4][2], bl[4][2];
#pragma unroll
            for (int mi = 0; mi < 4; mi++) {
                int r0 = wm * 64 + mi * 16 + gid;
                uint32_t c0 = (kcol + 2 * tig) * 2;
                const unsigned char* pAh = base + (uint32_t)r0 * ROWB + c0;
                const unsigned char* pAl = base + TILE_SM + (uint32_t)r0 * ROWB + c0;
                ah[mi][0] = *(const uint32_t*)(pAh);
                ah[mi][1] = *(const uint32_t*)(pAh + 8 * ROWB);
                ah[mi][2] = *(const uint32_t*)(pAh + 16);
                ah[mi][3] = *(const uint32_t*)(pAh + 8 * ROWB + 16);
                al[mi][0] = *(const uint32_t*)(pAl);
                al[mi][1] = *(const uint32_t*)(pAl + 8 * ROWB);
                al[mi][2] = *(const uint32_t*)(pAl + 16);
                al[mi][3] = *(const uint32_t*)(pAl + 8 * ROWB + 16);
            }
#pragma unroll
            for (int ni = 0; ni < 4; ni++) {
                int rn = wn * 32 + ni * 8 + gid;
                uint32_t c0 = (kcol + 2 * tig) * 2;
                const unsigned char* pBh = base + 2 * TILE_SM + (uint32_t)rn * ROWB + c0;
                const unsigned char* pBl = base + 3 * TILE_SM + (uint32_t)rn * ROWB + c0;
                bh[ni][0] = *(const uint32_t*)(pBh);
                bh[ni][1] = *(const uint32_t*)(pBh + 16);
                bl[ni][0] = *(const uint32_t*)(pBl);
                bl[ni][1] = *(const uint32_t*)(pBl + 16);
            }
#pragma unroll
            for (int mi = 0; mi < 4; mi++)
#pragma unroll
                for (int ni = 0; ni < 4; ni++) {
                    mma16816(acc[mi][ni], ah[mi], bh[ni]);
                    mma16816(acc[mi][ni], ah[mi], bl[ni]);
                    mma16816(acc[mi][ni], al[mi], bh[ni]);
                }
        }
        __syncthreads();
    }

    // Epilogue: d0,d1 -> (row, col..col+1); d2,d3 -> (row+8, ...)
#pragma unroll
    for (int mi = 0; mi < 4; mi++) {
#pragma unroll
        for (int half = 0; half < 2; half++) {
            int m = mt * TM + wm * 64 + mi * 16 + gid + half * 8;
            int tt = m >> 5, bb = m & 31;
            float* orow = out + (size_t)bb * ((size_t)T * V) + (size_t)tt * V;
#pragma unroll
            for (int ni = 0; ni < 4; ni++) {
                int v = nt * TN + wn * 32 + ni * 8 + 2 * tig;
                float2 bo = *(const float2*)(bout + v);
                float2 o;
                o.x = acc[mi][ni][half * 2 + 0] + bo.x;
                o.y = acc[mi][ni][half * 2 + 1] + bo.y;
                *(float2*)(orow + v) = o;
            }
        }
    }
}

// ---------------- fp32 SGEMM for the xW precompute ----------------
__global__ __launch_bounds__(256, 2) void sgemm_xw(
    const float* __restrict__ Aext, const float* __restrict__ Bw,
    const float* __restrict__ bias1, const float* __restrict__ bias2,
    const int* __restrict__ caps)
{
    __shared__ float As[8][128];
    __shared__ float Bs[8][128];

    const int tid = threadIdx.x;
    const int bx = blockIdx.x, by = blockIdx.y;
    const int tx = tid & 15, ty = tid >> 4;
    const int ldRow = tid >> 1;
    const int ldCol = (tid & 1) * 4;

    const int gRowA = by * 128 + ldRow;
    const float* aptr;
    {
        int b = gRowA & 31, t = gRowA >> 5;
        int token = caps[b * T + t];
        aptr = Aext + (size_t)token * H + ldCol;
    }
    const int gRowB = bx * 128 + ldRow;
    const float* bptr = Bw + (size_t)gRowB * (2 * H) + H + ldCol;  // ctx/W_ih not used; this is x-part: offset 0

    // NOTE: x part of W_ih is columns [0, H); fix pointer:
    bptr = Bw + (size_t)gRowB * (2 * H) + ldCol;

    float acc[8][8];
#pragma unroll
    for (int i = 0; i < 8; i++)
#pragma unroll
        for (int j = 0; j < 8; j++) acc[i][j] = 0.f;

    float4 av = *(const float4*)(aptr);
    float4 bv = *(const float4*)(bptr);

    for (int k0 = 0; k0 < H; k0 += 8) {
        As[ldCol + 0][ldRow] = av.x; As[ldCol + 1][ldRow] = av.y;
        As[ldCol + 2][ldRow] = av.z; As[ldCol + 3][ldRow] = av.w;
        Bs[ldCol + 0][ldRow] = bv.x; Bs[ldCol + 1][ldRow] = bv.y;
        Bs[ldCol + 2][ldRow] = bv.z; Bs[ldCol + 3][ldRow] = bv.w;
        __syncthreads();
        if (k0 + 8 < H) {
            av = *(const float4*)(aptr + k0 + 8);
            bv = *(const float4*)(bptr + k0 + 8);
        }
#pragma unroll
        for (int kk = 0; kk < 8; kk++) {
            float4 a0 = *(const float4*)&As[kk][ty * 8];
            float4 a1 = *(const float4*)&As[kk][ty * 8 + 4];
            float4 b0 = *(const float4*)&Bs[kk][tx * 8];
            float4 b1 = *(const float4*)&Bs[kk][tx * 8 + 4];
            float a[8] = {a0.x, a0.y, a0.z, a0.w, a1.x, a1.y, a1.z, a1.w};
            float bb[8] = {b0.x, b0.y, b0.z, b0.w, b1.x, b1.y, b1.z, b1.w};
#pragma unroll
            for (int i = 0; i < 8; i++)
#pragma unroll
                for (int j = 0; j < 8; j++) acc[i][j] += a[i] * bb[j];
        }
        __syncthreads();
    }

#pragma unroll
    for (int i = 0; i < 8; i++) {
        int m = by * 128 + ty * 8 + i;
#pragma unroll
        for (int j = 0; j < 8; j += 4) {
            int n = bx * 128 + tx * 8 + j;
            float4 o;
            o.x = acc[i][j + 0] + bias1[n + 0] + bias2[n + 0];
            o.y = acc[i][j + 1] + bias1[n + 1] + bias2[n + 1];
            o.z = acc[i][j + 2] + bias1[n + 2] + bias2[n + 2];
            o.w = acc[i][j + 3] + bias1[n + 3] + bias2[n + 3];
            *(float4*)&g_xW[(size_t)m * G4 + n] = o;
        }
    }
}

// ---------------- q = h @ attn_W^T ----------------
__global__ __launch_bounds__(256) void k_q(const float* __restrict__ attnW, int t)
{
    __shared__ float sH[32][68];
    __shared__ float sW[8][68];
    const float* hbase = g_Hbuf + (size_t)t * B * H;
    const int tid = threadIdx.x;
    const int n0 = blockIdx.x * 8;
    const int b = tid >> 3, ji = tid & 7;
    float acc = 0.f;

    for (int k0 = 0; k0 < H; k0 += 64) {
        __syncthreads();
        {
            int row = tid >> 3;
            int kk = (tid & 7) * 8;
            const float* p = hbase + row * H + k0 + kk;
            *(float4*)&sH[row][kk] = *(const float4*)p;
            *(float4*)&sH[row][kk + 4] = *(const float4*)(p + 4);
            if (tid < 64) {
                int wr = tid >> 3;
                int kw = (tid & 7) * 8;
                const float* wp = attnW + (size_t)(n0 + wr) * H + k0 + kw;
                *(float4*)&sW[wr][kw] = *(const float4*)wp;
                *(float4*)&sW[wr][kw + 4] = *(const float4*)(wp + 4);
            }
        }
        __syncthreads();
#pragma unroll
        for (int kk = 0; kk < 64; kk += 4) {
            float4 a = *(const float4*)&sH[b][kk];
            float4 w = *(const float4*)&sW[ji][kk];
            acc += a.x * w.x + a.y * w.y + a.z * w.z + a.w * w.w;
        }
    }
    g_q[b * H + n0 + ji] = acc;
}

// ---------------- fused scores + softmax + ctx (one block per b) ----------------
__global__ __launch_bounds__(256) void k_attn(const float* __restrict__ mem)
{
    __shared__ float sQ[H];
    __shared__ float sw_[S];
    __shared__ float red[8];
    const int b = blockIdx.x;
    const int tid = threadIdx.x;
    const int warp = tid >> 5, lane = tid & 31;

    for (int i = tid; i < H; i += 256) sQ[i] = g_q[b * H + i];
    __syncthreads();

    for (int s = warp; s < S; s += 8) {
        const float* mrow = mem + ((size_t)b * S + s) * H;
        float acc = 0.f;
#pragma unroll
        for (int i = 0; i < 8; i++) {
            int k = i * 128 + lane * 4;
            float4 m4 = *(const float4*)(mrow + k);
            float4 q4 = *(const float4*)&sQ[k];
            acc += m4.x * q4.x + m4.y * q4.y + m4.z * q4.z + m4.w * q4.w;
        }
#pragma unroll
        for (int o = 16; o > 0; o >>= 1) acc += __shfl_down_sync(0xffffffffu, acc, o);
        if (lane == 0) sw_[s] = acc;
    }
    __syncthreads();

    float v = (tid < S) ? sw_[tid] : -1e30f;
    float m = v;
#pragma unroll
    for (int o = 16; o > 0; o >>= 1) m = fmaxf(m, __shfl_xor_sync(0xffffffffu, m, o));
    if (lane == 0) red[warp] = m;
    __syncthreads();
    float bm = red[0];
#pragma unroll
    for (int w = 1; w < 8; w++) bm = fmaxf(bm, red[w]);
    float e = (tid < S) ? expf(v - bm) : 0.f;
    __syncthreads();
    float sacc = e;
#pragma unroll
    for (int o = 16; o > 0; o >>= 1) sacc += __shfl_xor_sync(0xffffffffu, sacc, o);
    if (lane == 0) red[warp] = sacc;
    __syncthreads();
    float total = 0.f;
#pragma unroll
    for (int w = 0; w < 8; w++) total += red[w];
    if (tid < S) sw_[tid] = e / total;
    __syncthreads();

    for (int hh = tid; hh < H; hh += 256) {
        const float* mb = mem + (size_t)b * S * H + hh;
        float acc = 0.f;
#pragma unroll 7
        for (int s2 = 0; s2 < S; s2++) acc += sw_[s2] * mb[(size_t)s2 * H];
        g_ctx[b * H + hh] = acc;
    }
}

// ---------------- gates + LSTM pointwise ----------------
__global__ __launch_bounds__(256) void k_gates(const float* __restrict__ W_ih,
                                               const float* __restrict__ W_hh, int t)
{
    __shared__ float sA[32][68];
    __shared__ float sW[32][68];
    const int tid = threadIdx.x;
    const int j0 = blockIdx.x * 8;
    const int b = tid >> 3, ji = tid & 7;
    float acc[4] = {0.f, 0.f, 0.f, 0.f};
    const float* hprev = g_Hbuf + (size_t)t * B * H;

    for (int src = 0; src < 2; src++) {
        const float* Ain = (src == 0) ? g_ctx : hprev;
        const float* Wbase = (src == 0) ? W_ih : W_hh;
        const int ldw = (src == 0) ? 2 * H : H;
        const int off = (src == 0) ? H : 0;
        for (int k0 = 0; k0 < H; k0 += 64) {
            __syncthreads();
            {
                int row = tid >> 3;
                int kk = (tid & 7) * 8;
                const float* p = Ain + row * H + k0 + kk;
                *(float4*)&sA[row][kk] = *(const float4*)p;
                *(float4*)&sA[row][kk + 4] = *(const float4*)(p + 4);
                int n = (row >> 3) * H + j0 + (row & 7);
                const float* wp = Wbase + (size_t)n * ldw + off + k0 + kk;
                *(float4*)&sW[row][kk] = *(const float4*)wp;
                *(float4*)&sW[row][kk + 4] = *(const float4*)(wp + 4);
            }
            __syncthreads();
#pragma unroll
            for (int kk = 0; kk < 64; kk += 4) {
                float4 a = *(const float4*)&sA[b][kk];
#pragma unroll
                for (int g = 0; g < 4; g++) {
                    float4 w = *(const float4*)&sW[g * 8 + ji][kk];
                    acc[g] += a.x * w.x + a.y * w.y + a.z * w.z + a.w * w.w;
                }
            }
        }
    }

    const int j = j0 + ji;
    const size_t xbase = ((size_t)t * B + b) * G4 + j;
    float gi = acc[0] + g_xW[xbase];
    float gf = acc[1] + g_xW[xbase + H];
    float gg = acc[2] + g_xW[xbase + 2 * H];
    float go = acc[3] + g_xW[xbase + 3 * H];
    gi = 1.f / (1.f + expf(-gi));
    gf = 1.f / (1.f + expf(-gf));
    gg = tanhf(gg);
    go = 1.f / (1.f + expf(-go));
    float c_old = g_cbuf[(t & 1) * B * H + b * H + j];
    float c_new = gf * c_old + gi * gg;
    float h_new = go * tanhf(c_new);
    g_cbuf[((t + 1) & 1) * B * H + b * H + j] = c_new;
    g_Hbuf[(size_t)(t + 1) * B * H + b * H + j] = h_new;
}

// ---------------- tail: final h, c ----------------
__global__ void k_tail(float* __restrict__ out)
{
    int i = blockIdx.x * blockDim.x + threadIdx.x;
    if (i < B * H) {
        out[(size_t)B * T * V + i] = g_Hbuf[(size_t)T * B * H + i];
        out[(size_t)B * T * V + B * H + i] = g_cbuf[0 * B * H + i];
    }
}

// ---------------- launch ----------------
extern "C" void kernel_launch(void* const* d_in, const int* in_sizes, int n_in,
                              void* d_out, int out_size)
{
    const float* memory   = (const float*)d_in[0];
    const int*   captions = (const int*)d_in[1];
    const float* emb      = (const float*)d_in[2];
    const float* attnW    = (const float*)d_in[3];
    const float* W_ih     = (const float*)d_in[4];
    const float* W_hh     = (const float*)d_in[5];
    const float* b_ih     = (const float*)d_in[6];
    const float* b_hh     = (const float*)d_in[7];
    const float* W_out    = (const float*)d_in[8];
    const float* b_out    = (const float*)d_in[9];
    float* out = (float*)d_out;

    cudaFuncSetAttribute(k_mma2, cudaFuncAttributeMaxDynamicSharedMemorySize, SMEM_MMA);

    k_zero<<<(B * H + 255) / 256, 256>>>();
    k_convW<<<V, 256>>>(W_out);

    {
        dim3 g(G4 / 128, (T * B) / 128);   // (32, 16)
        sgemm_xw<<<g, 256>>>(emb, W_ih, b_ih, b_hh, captions);
    }

    for (int t = 0; t < T; t++) {
        k_q<<<128, 256>>>(attnW, t);
        k_attn<<<B, 256>>>(memory);
        k_gates<<<128, 256>>>(W_ih, W_hh, t);
    }

    k_convA<<<T * B, 256>>>();
    {
        dim3 g(T * B / TM, V / TN);        // (16, 250): m fastest for W-tile L2 reuse
        k_mma2<<<g, 256, SMEM_MMA>>>(b_out, out);
    }

    k_tail<<<(B * H + 255) / 256, 256>>>(out);
}

// round 7
// speedup vs baseline: 1.2122x; 1.1868x over previous
#include <cuda_runtime.h>
#include <cuda_bf16.h>
#include <math.h>
#include <stdint.h>

#define B  32
#define S  196
#define T  64
#define H  1024
#define V  32000
#define G4 4096

// MMA GEMM tiling
#define TM 128
#define TN 128
#define KC 32
#define NKC (H / KC)                 // 32 chunks
#define ROWB 80                      // SMEM row pitch bytes (64 data + 16 pad) -> conflict-free
#define TILE_SM (128 * ROWB)         // 10240 B per tile
#define BUF_SM (4 * TILE_SM)         // Ah, Al, Bh, Bl
#define SMEM_MMA (2 * BUF_SM)        // 81920 B double-buffered

// ---------------- scratch (static device memory; no allocs) ----------------
__device__ float g_xW[(size_t)T * B * G4];        // [t][b][4H]
__device__ float g_Hbuf[(size_t)(T + 1) * B * H]; // h states; slot t+1 = h after step t
__device__ float g_cbuf[2 * B * H];
__device__ float g_scores[B * S];
__device__ float g_ctx[B * H];
__device__ float g_M2[(size_t)B * S * H];         // memory @ attn_W  [b][s][h]

// bf16 hi/lo split staging, plain row-major [rows][H]
__device__ __align__(16) unsigned char g_Whi[(size_t)V * H * 2];
__device__ __align__(16) unsigned char g_Wlo[(size_t)V * H * 2];
__device__ __align__(16) unsigned char g_Ahi[(size_t)T * B * H * 2];
__device__ __align__(16) unsigned char g_Alo[(size_t)T * B * H * 2];

__device__ __forceinline__ void split2(float x, unsigned short& hi, unsigned short& lo) {
    __nv_bfloat16 h = __float2bfloat16(x);
    float hf = __bfloat162float(h);
    __nv_bfloat16 l = __float2bfloat16(x - hf);
    hi = *reinterpret_cast<unsigned short*>(&h);
    lo = *reinterpret_cast<unsigned short*>(&l);
}

// ---------------- convert W_out -> bf16 hi/lo; block 0 also zeros h0/c0 ----------------
__global__ void k_convW(const float* __restrict__ W) {
    int n = blockIdx.x;               // 0..V-1
    int k0 = threadIdx.x * 4;         // 0..1020
    if (n == 0) {
        for (int i = threadIdx.x; i < B * H; i += 256) { g_Hbuf[i] = 0.f; g_cbuf[i] = 0.f; }
    }
    float4 w = *(const float4*)(W + (size_t)n * H + k0);
    unsigned short h0, h1, h2, h3, l0, l1, l2, l3;
    split2(w.x, h0, l0); split2(w.y, h1, l1); split2(w.z, h2, l2); split2(w.w, h3, l3);
    uint2 hv = make_uint2((uint32_t)h0 | ((uint32_t)h1 << 16), (uint32_t)h2 | ((uint32_t)h3 << 16));
    uint2 lv = make_uint2((uint32_t)l0 | ((uint32_t)l1 << 16), (uint32_t)l2 | ((uint32_t)l3 << 16));
    *(uint2*)(g_Whi + ((size_t)n * H + k0) * 2) = hv;
    *(uint2*)(g_Wlo + ((size_t)n * H + k0) * 2) = lv;
}

// ---------------- convert h matrix (row m = t*32+b -> h_{t+1}[b]) ----------------
__global__ void k_convA() {
    int m = blockIdx.x;               // 0..2047
    int k0 = threadIdx.x * 4;
    float4 w = *(const float4*)(g_Hbuf + (size_t)(m + B) * H + k0);
    unsigned short h0, h1, h2, h3, l0, l1, l2, l3;
    split2(w.x, h0, l0); split2(w.y, h1, l1); split2(w.z, h2, l2); split2(w.w, h3, l3);
    uint2 hv = make_uint2((uint32_t)h0 | ((uint32_t)h1 << 16), (uint32_t)h2 | ((uint32_t)h3 << 16));
    uint2 lv = make_uint2((uint32_t)l0 | ((uint32_t)l1 << 16), (uint32_t)l2 | ((uint32_t)l3 << 16));
    *(uint2*)(g_Ahi + ((size_t)m * H + k0) * 2) = hv;
    *(uint2*)(g_Alo + ((size_t)m * H + k0) * 2) = lv;
}

// ---------------- mma / ldmatrix helpers ----------------
__device__ __forceinline__ void mma16816(float* d, const uint32_t* a, const uint32_t* b) {
    asm volatile(
        "mma.sync.aligned.m16n8k16.row.col.f32.bf16.bf16.f32 "
        "{%0,%1,%2,%3}, {%4,%5,%6,%7}, {%8,%9}, {%0,%1,%2,%3};"
        : "+f"(d[0]), "+f"(d[1]), "+f"(d[2]), "+f"(d[3])
        : "r"(a[0]), "r"(a[1]), "r"(a[2]), "r"(a[3]), "r"(b[0]), "r"(b[1]));
}

__device__ __forceinline__ void ldsm_x4(uint32_t* r, uint32_t a) {
    asm volatile("ldmatrix.sync.aligned.m8n8.x4.shared.b16 {%0,%1,%2,%3}, [%4];"
                 : "=r"(r[0]), "=r"(r[1]), "=r"(r[2]), "=r"(r[3]) : "r"(a));
}
__device__ __forceinline__ void ldsm_x2(uint32_t* r, uint32_t a) {
    asm volatile("ldmatrix.sync.aligned.m8n8.x2.shared.b16 {%0,%1}, [%2];"
                 : "=r"(r[0]), "=r"(r[1]) : "r"(a));
}

__device__ __forceinline__ uint32_t smem_u32(const void* p) {
    uint32_t a;
    asm("{ .reg .u64 t; cvta.to.shared.u64 t, %1; cvt.u32.u64 %0, t; }" : "=r"(a) : "l"(p));
    return a;
}

__device__ __forceinline__ void cp16(void* dst_smem, const void* src_gmem) {
    uint32_t d;
    asm("{ .reg .u64 t; cvta.to.shared.u64 t, %1; cvt.u32.u64 %0, t; }" : "=r"(d) : "l"(dst_smem));
    asm volatile("cp.async.ca.shared.global [%0], [%1], 16;" :: "r"(d), "l"(src_gmem) : "memory");
}

// ---------------- tensor-core vocab GEMM ----------------
__global__ __launch_bounds__(256) void k_mma2(const float* __restrict__ bout,
                                              float* __restrict__ out) {
    extern __shared__ __align__(16) unsigned char sm[];
    const uint32_t sbase = smem_u32(sm);
    const int tid = threadIdx.x;
    const int wid = tid >> 5, lane = tid & 31;
    const int gid = lane >> 2, tig = lane & 3;
    const int wm = wid >> 2, wn = wid & 3;           // 2 x 4 warp grid
    const int mt = blockIdx.x, nt = blockIdx.y;

    const size_t aRow0 = (size_t)mt * TM;
    const size_t bRow0 = (size_t)nt * TN;

    // ldmatrix lane-address components (constant per thread)
    const uint32_t aLaneRow = (uint32_t)((lane & 7) + ((lane >> 3) & 1) * 8);
    const uint32_t aLaneCol = (uint32_t)((lane >> 4) * 16);
    const uint32_t bLaneRow = (uint32_t)(lane & 7);
    const uint32_t bLaneCol = (uint32_t)(((lane >> 3) & 1) * 16);

    float acc[4][4][4];
#pragma unroll
    for (int i = 0; i < 4; i++)
#pragma unroll
        for (int j = 0; j < 4; j++)
#pragma unroll
            for (int q = 0; q < 4; q++) acc[i][j][q] = 0.f;

    auto load_chunk = [&](int kc, int buf) {
        unsigned char* base = sm + buf * BUF_SM;
        const int kOff = kc * KC;
#pragma unroll
        for (int half = 0; half < 2; half++) {
            int idx = tid + half * 256;              // 0..511
            int row = idx >> 2, quad = idx & 3;
            size_t gA = ((aRow0 + row) * (size_t)H + kOff + quad * 8) * 2;
            size_t gB = ((bRow0 + row) * (size_t)H + kOff + quad * 8) * 2;
            uint32_t so = row * ROWB + quad * 16;
            cp16(base + so,               g_Ahi + gA);
            cp16(base + TILE_SM + so,     g_Alo + gA);
            cp16(base + 2 * TILE_SM + so, g_Whi + gB);
            cp16(base + 3 * TILE_SM + so, g_Wlo + gB);
        }
        asm volatile("cp.async.commit_group;" ::: "memory");
    };

    load_chunk(0, 0);

    for (int kc = 0; kc < NKC; kc++) {
        const int cur = kc & 1;
        if (kc + 1 < NKC) {
            load_chunk(kc + 1, cur ^ 1);
            asm volatile("cp.async.wait_group 1;" ::: "memory");
        } else {
            asm volatile("cp.async.wait_group 0;" ::: "memory");
        }
        __syncthreads();

        const uint32_t base = sbase + cur * BUF_SM;
#pragma unroll
        for (int ks = 0; ks < 2; ks++) {
            const uint32_t kb = (uint32_t)(ks * 32);     // byte offset of k-step
            uint32_t ah[4][4], al[4][4], bh[4][2], bl[4][2];
#pragma unroll
            for (int mi = 0; mi < 4; mi++) {
                uint32_t r = (uint32_t)(wm * 64 + mi * 16) + aLaneRow;
                uint32_t a = base + r * ROWB + kb + aLaneCol;
                ldsm_x4(ah[mi], a);
                ldsm_x4(al[mi], a + TILE_SM);
            }
#pragma unroll
            for (int ni = 0; ni < 4; ni++) {
                uint32_t r = (uint32_t)(wn * 32 + ni * 8) + bLaneRow;
                uint32_t a = base + 2 * TILE_SM + r * ROWB + kb + bLaneCol;
                ldsm_x2(bh[ni], a);
                ldsm_x2(bl[ni], a + TILE_SM);
            }
#pragma unroll
            for (int mi = 0; mi < 4; mi++)
#pragma unroll
                for (int ni = 0; ni < 4; ni++) {
                    mma16816(acc[mi][ni], ah[mi], bh[ni]);
                    mma16816(acc[mi][ni], ah[mi], bl[ni]);
                    mma16816(acc[mi][ni], al[mi], bh[ni]);
                }
        }
        __syncthreads();
    }

#pragma unroll
    for (int mi = 0; mi < 4; mi++) {
#pragma unroll
        for (int half = 0; half < 2; half++) {
            int m = mt * TM + wm * 64 + mi * 16 + gid + half * 8;
            int tt = m >> 5, bb = m & 31;
            float* orow = out + (size_t)bb * ((size_t)T * V) + (size_t)tt * V;
#pragma unroll
            for (int ni = 0; ni < 4; ni++) {
                int v = nt * TN + wn * 32 + ni * 8 + 2 * tig;
                float2 bo = *(const float2*)(bout + v);
                float2 o;
                o.x = acc[mi][ni][half * 2 + 0] + bo.x;
                o.y = acc[mi][ni][half * 2 + 1] + bo.y;
                *(float2*)(orow + v) = o;
            }
        }
    }
}

// ---------------- fp32 SGEMM: xW precompute ----------------
__global__ __launch_bounds__(256, 2) void sgemm_xw(
    const float* __restrict__ Aext, const float* __restrict__ Bw,
    const float* __restrict__ bias1, const float* __restrict__ bias2,
    const int* __restrict__ caps)
{
    __shared__ float As[8][128];
    __shared__ float Bs[8][128];

    const int tid = threadIdx.x;
    const int bx = blockIdx.x, by = blockIdx.y;
    const int tx = tid & 15, ty = tid >> 4;
    const int ldRow = tid >> 1;
    const int ldCol = (tid & 1) * 4;

    const int gRowA = by * 128 + ldRow;
    const float* aptr;
    {
        int b = gRowA & 31, t = gRowA >> 5;
        int token = caps[b * T + t];
        aptr = Aext + (size_t)token * H + ldCol;
    }
    const int gRowB = bx * 128 + ldRow;
    const float* bptr = Bw + (size_t)gRowB * (2 * H) + ldCol;   // x-part: cols [0, H)

    float acc[8][8];
#pragma unroll
    for (int i = 0; i < 8; i++)
#pragma unroll
        for (int j = 0; j < 8; j++) acc[i][j] = 0.f;

    float4 av = *(const float4*)(aptr);
    float4 bv = *(const float4*)(bptr);

    for (int k0 = 0; k0 < H; k0 += 8) {
        As[ldCol + 0][ldRow] = av.x; As[ldCol + 1][ldRow] = av.y;
        As[ldCol + 2][ldRow] = av.z; As[ldCol + 3][ldRow] = av.w;
        Bs[ldCol + 0][ldRow] = bv.x; Bs[ldCol + 1][ldRow] = bv.y;
        Bs[ldCol + 2][ldRow] = bv.z; Bs[ldCol + 3][ldRow] = bv.w;
        __syncthreads();
        if (k0 + 8 < H) {
            av = *(const float4*)(aptr + k0 + 8);
            bv = *(const float4*)(bptr + k0 + 8);
        }
#pragma unroll
        for (int kk = 0; kk < 8; kk++) {
            float4 a0 = *(const float4*)&As[kk][ty * 8];
            float4 a1 = *(const float4*)&As[kk][ty * 8 + 4];
            float4 b0 = *(const float4*)&Bs[kk][tx * 8];
            float4 b1 = *(const float4*)&Bs[kk][tx * 8 + 4];
            float a[8] = {a0.x, a0.y, a0.z, a0.w, a1.x, a1.y, a1.z, a1.w};
            float bb[8] = {b0.x, b0.y, b0.z, b0.w, b1.x, b1.y, b1.z, b1.w};
#pragma unroll
            for (int i = 0; i < 8; i++)
#pragma unroll
                for (int j = 0; j < 8; j++) acc[i][j] += a[i] * bb[j];
        }
        __syncthreads();
    }

#pragma unroll
    for (int i = 0; i < 8; i++) {
        int m = by * 128 + ty * 8 + i;
#pragma unroll
        for (int j = 0; j < 8; j += 4) {
            int n = bx * 128 + tx * 8 + j;
            float4 o;
            o.x = acc[i][j + 0] + bias1[n + 0] + bias2[n + 0];
            o.y = acc[i][j + 1] + bias1[n + 1] + bias2[n + 1];
            o.z = acc[i][j + 2] + bias1[n + 2] + bias2[n + 2];
            o.w = acc[i][j + 3] + bias1[n + 3] + bias2[n + 3];
            *(float4*)&g_xW[(size_t)m * G4 + n] = o;
        }
    }
}

// ---------------- fp32 SGEMM: M2 = memory @ attn_W  (B directly, no transpose) ----------------
// M2[r, j] = sum_k mem[r,k] * attn_W[k, j]; r = b*S+s over 6272 = 49*128, j over 1024.
__global__ __launch_bounds__(256, 2) void sgemm_M2(
    const float* __restrict__ mem, const float* __restrict__ attnW)
{
    __shared__ float As[8][128];
    __shared__ float Bs[8][128];

    const int tid = threadIdx.x;
    const int bx = blockIdx.x, by = blockIdx.y;
    const int tx = tid & 15, ty = tid >> 4;

    // A loader (rows of mem)
    const int ldRow = tid >> 1;
    const int ldCol = (tid & 1) * 4;
    const float* aptr = mem + (size_t)(by * 128 + ldRow) * H + ldCol;

    // B loader: Bs[kk][j] = attn_W[(k0+kk)*H + n0 + j]; thread: kk=tid>>5, j4=(tid&31)*4
    const int bkk = tid >> 5;
    const int bj4 = (tid & 31) * 4;
    const float* bptr = attnW + (size_t)bkk * H + bx * 128 + bj4;

    float acc[8][8];
#pragma unroll
    for (int i = 0; i < 8; i++)
#pragma unroll
        for (int j = 0; j < 8; j++) acc[i][j] = 0.f;

    float4 av = *(const float4*)(aptr);
    float4 bv = *(const float4*)(bptr);

    for (int k0 = 0; k0 < H; k0 += 8) {
        As[ldCol + 0][ldRow] = av.x; As[ldCol + 1][ldRow] = av.y;
        As[ldCol + 2][ldRow] = av.z; As[ldCol + 3][ldRow] = av.w;
        *(float4*)&Bs[bkk][bj4] = bv;
        __syncthreads();
        if (k0 + 8 < H) {
            av = *(const float4*)(aptr + k0 + 8);
            bv = *(const float4*)(bptr + (size_t)(k0 + 8) * H);
        }
#pragma unroll
        for (int kk = 0; kk < 8; kk++) {
            float4 a0 = *(const float4*)&As[kk][ty * 8];
            float4 a1 = *(const float4*)&As[kk][ty * 8 + 4];
            float4 b0 = *(const float4*)&Bs[kk][tx * 8];
            float4 b1 = *(const float4*)&Bs[kk][tx * 8 + 4];
            float a[8] = {a0.x, a0.y, a0.z, a0.w, a1.x, a1.y, a1.z, a1.w};
            float bb[8] = {b0.x, b0.y, b0.z, b0.w, b1.x, b1.y, b1.z, b1.w};
#pragma unroll
            for (int i = 0; i < 8; i++)
#pragma unroll
                for (int j = 0; j < 8; j++) acc[i][j] += a[i] * bb[j];
        }
        __syncthreads();
    }

#pragma unroll
    for (int i = 0; i < 8; i++) {
        int r = by * 128 + ty * 8 + i;
#pragma unroll
        for (int j = 0; j < 8; j += 4) {
            int n = bx * 128 + tx * 8 + j;
            float4 o = make_float4(acc[i][j], acc[i][j + 1], acc[i][j + 2], acc[i][j + 3]);
            *(float4*)&g_M2[(size_t)r * H + n] = o;
        }
    }
}

// ---------------- scores[b][s] = h_t[b] . M2[b][s] ----------------
__global__ __launch_bounds__(256) void k_score(int t)
{
    __shared__ float sHv[H];
    const int sc = blockIdx.x;   // 0..6 (28 s each)
    const int b = blockIdx.y;
    const int tid = threadIdx.x;
    const float* hrow = g_Hbuf + (size_t)t * B * H + (size_t)b * H;
    for (int i = tid; i < H; i += 256) sHv[i] = hrow[i];
    __syncthreads();
    const int warp = tid >> 5, lane = tid & 31;
    for (int si = warp; si < 28; si += 8) {
        int s = sc * 28 + si;
        const float* mrow = g_M2 + ((size_t)b * S + s) * H;
        float acc = 0.f;
#pragma unroll
        for (int i = 0; i < 8; i++) {
            int k = i * 128 + lane * 4;
            float4 m4 = *(const float4*)(mrow + k);
            float4 q4 = *(const float4*)&sHv[k];
            acc += m4.x * q4.x + m4.y * q4.y + m4.z * q4.z + m4.w * q4.w;
        }
#pragma unroll
        for (int o = 16; o > 0; o >>= 1) acc += __shfl_down_sync(0xffffffffu, acc, o);
        if (lane == 0) g_scores[b * S + s] = acc;
    }
}

// ---------------- softmax + ctx ----------------
__global__ __launch_bounds__(256) void k_softctx(const float* __restrict__ mem)
{
    __shared__ float sw_[S];
    __shared__ float red[8];
    const int b = blockIdx.y;
    const int tid = threadIdx.x;
    const int warp = tid >> 5, lane = tid & 31;

    float v = (tid < S) ? g_scores[b * S + tid] : -1e30f;
    float m = v;
#pragma unroll
    for (int o = 16; o > 0; o >>= 1) m = fmaxf(m, __shfl_xor_sync(0xffffffffu, m, o));
    if (lane == 0) red[warp] = m;
    __syncthreads();
    float bm = red[0];
#pragma unroll
    for (int w = 1; w < 8; w++) bm = fmaxf(bm, red[w]);
    float e = (tid < S) ? expf(v - bm) : 0.f;
    __syncthreads();
    float sacc = e;
#pragma unroll
    for (int o = 16; o > 0; o >>= 1) sacc += __shfl_xor_sync(0xffffffffu, sacc, o);
    if (lane == 0) red[warp] = sacc;
    __syncthreads();
    float total = 0.f;
#pragma unroll
    for (int w = 0; w < 8; w++) total += red[w];
    if (tid < S) sw_[tid] = e / total;
    __syncthreads();

    int h = blockIdx.x * 256 + tid;       // gridDim.x = 4
    const float* mb = mem + (size_t)b * S * H + h;
    float acc = 0.f;
#pragma unroll 7
    for (int s2 = 0; s2 < S; s2++) acc += sw_[s2] * mb[(size_t)s2 * H];
    g_ctx[b * H + h] = acc;
}

// ---------------- gates + LSTM pointwise ----------------
__global__ __launch_bounds__(256) void k_gates(const float* __restrict__ W_ih,
                                               const float* __restrict__ W_hh, int t)
{
    __shared__ float sA[32][68];
    __shared__ float sW[32][68];
    const int tid = threadIdx.x;
    const int j0 = blockIdx.x * 8;
    const int b = tid >> 3, ji = tid & 7;
    float acc[4] = {0.f, 0.f, 0.f, 0.f};
    const float* hprev = g_Hbuf + (size_t)t * B * H;

    for (int src = 0; src < 2; src++) {
        const float* Ain = (src == 0) ? g_ctx : hprev;
        const float* Wbase = (src == 0) ? W_ih : W_hh;
        const int ldw = (src == 0) ? 2 * H : H;
        const int off = (src == 0) ? H : 0;
        for (int k0 = 0; k0 < H; k0 += 64) {
            __syncthreads();
            {
                int row = tid >> 3;
                int kk = (tid & 7) * 8;
                const float* p = Ain + row * H + k0 + kk;
                *(float4*)&sA[row][kk] = *(const float4*)p;
                *(float4*)&sA[row][kk + 4] = *(const float4*)(p + 4);
                int n = (row >> 3) * H + j0 + (row & 7);
                const float* wp = Wbase + (size_t)n * ldw + off + k0 + kk;
                *(float4*)&sW[row][kk] = *(const float4*)wp;
                *(float4*)&sW[row][kk + 4] = *(const float4*)(wp + 4);
            }
            __syncthreads();
#pragma unroll
            for (int kk = 0; kk < 64; kk += 4) {
                float4 a = *(const float4*)&sA[b][kk];
#pragma unroll
                for (int g = 0; g < 4; g++) {
                    float4 w = *(const float4*)&sW[g * 8 + ji][kk];
                    acc[g] += a.x * w.x + a.y * w.y + a.z * w.z + a.w * w.w;
                }
            }
        }
    }

    const int j = j0 + ji;
    const size_t xbase = ((size_t)t * B + b) * G4 + j;
    float gi = acc[0] + g_xW[xbase];
    float gf = acc[1] + g_xW[xbase + H];
    float gg = acc[2] + g_xW[xbase + 2 * H];
    float go = acc[3] + g_xW[xbase + 3 * H];
    gi = 1.f / (1.f + expf(-gi));
    gf = 1.f / (1.f + expf(-gf));
    gg = tanhf(gg);
    go = 1.f / (1.f + expf(-go));
    float c_old = g_cbuf[(t & 1) * B * H + b * H + j];
    float c_new = gf * c_old + gi * gg;
    float h_new = go * tanhf(c_new);
    g_cbuf[((t + 1) & 1) * B * H + b * H + j] = c_new;
    g_Hbuf[(size_t)(t + 1) * B * H + b * H + j] = h_new;
}

// ---------------- tail: final h, c ----------------
__global__ void k_tail(float* __restrict__ out)
{
    int i = blockIdx.x * blockDim.x + threadIdx.x;
    if (i < B * H) {
        out[(size_t)B * T * V + i] = g_Hbuf[(size_t)T * B * H + i];
        out[(size_t)B * T * V + B * H + i] = g_cbuf[0 * B * H + i];
    }
}

// ---------------- launch ----------------
extern "C" void kernel_launch(void* const* d_in, const int* in_sizes, int n_in,
                              void* d_out, int out_size)
{
    const float* memory   = (const float*)d_in[0];
    const int*   captions = (const int*)d_in[1];
    const float* emb      = (const float*)d_in[2];
    const float* attnW    = (const float*)d_in[3];
    const float* W_ih     = (const float*)d_in[4];
    const float* W_hh     = (const float*)d_in[5];
    const float* b_ih     = (const float*)d_in[6];
    const float* b_hh     = (const float*)d_in[7];
    const float* W_out    = (const float*)d_in[8];
    const float* b_out    = (const float*)d_in[9];
    float* out = (float*)d_out;

    cudaFuncSetAttribute(k_mma2, cudaFuncAttributeMaxDynamicSharedMemorySize, SMEM_MMA);

    // launch 1: W conversion (+ zero h0/c0 in block 0)
    k_convW<<<V, 256>>>(W_out);

    // launch 2: xW = emb[captions] @ W_ih_x^T + biases
    {
        dim3 g(G4 / 128, (T * B) / 128);   // (32, 16)
        sgemm_xw<<<g, 256>>>(emb, W_ih, b_ih, b_hh, captions);
    }

    // launch 3: M2 = memory @ attn_W
    {
        dim3 g(H / 128, (B * S) / 128);    // (8, 49)
        sgemm_M2<<<g, 256>>>(memory, attnW);
    }

    // launches 4..: recurrence (profiled slot #6 = k_gates at t=0)
    for (int t = 0; t < T; t++) {
        k_score<<<dim3(7, B), 256>>>(t);
        k_softctx<<<dim3(4, B), 256>>>(memory);
        k_gates<<<128, 256>>>(W_ih, W_hh, t);
    }

    k_convA<<<T * B, 256>>>();
    {
        dim3 g(T * B / TM, V / TN);        // (16, 250): m fastest for W-tile L2 reuse
        k_mma2<<<g, 256, SMEM_MMA>>>(b_out, out);
    }

    k_tail<<<(B * H + 255) / 256, 256>>>(out);
}

// round 10
// speedup vs baseline: 1.3170x; 1.0865x over previous
#include <cuda_runtime.h>
#include <cuda_bf16.h>
#include <math.h>
#include <stdint.h>

#define B  32
#define S  196
#define T  64
#define H  1024
#define V  32000
#define G4 4096

// MMA GEMM tiling
#define TM 128
#define TN 128
#define KC 32
#define NKC (H / KC)                 // 32 chunks
#define ROWB 80                      // SMEM row pitch bytes (64 data + 16 pad) -> conflict-free
#define TILE_SM (128 * ROWB)         // 10240 B per tile
#define BUF_SM (4 * TILE_SM)         // Ah, Al, Bh, Bl
#define SMEM_MMA (2 * BUF_SM)        // 81920 B double-buffered

// ---------------- scratch (static device memory; no allocs) ----------------
__device__ float g_xW[(size_t)T * B * G4];        // [t][b][4H]
__device__ float g_Hbuf[(size_t)(T + 1) * B * H]; // h states; slot t+1 = h after step t
__device__ float g_cbuf[2 * B * H];
__device__ float g_scores[B * S];
__device__ float g_ctx[B * H];
__device__ float g_M2[(size_t)B * S * H];         // memory @ attn_W  [b][s][h]

// bf16 hi/lo split staging, plain row-major [rows][H]
__device__ __align__(16) unsigned char g_Whi[(size_t)V * H * 2];
__device__ __align__(16) unsigned char g_Wlo[(size_t)V * H * 2];
__device__ __align__(16) unsigned char g_Ahi[(size_t)T * B * H * 2];
__device__ __align__(16) unsigned char g_Alo[(size_t)T * B * H * 2];

__device__ __forceinline__ void split2(float x, unsigned short& hi, unsigned short& lo) {
    __nv_bfloat16 h = __float2bfloat16(x);
    float hf = __bfloat162float(h);
    __nv_bfloat16 l = __float2bfloat16(x - hf);
    hi = *reinterpret_cast<unsigned short*>(&h);
    lo = *reinterpret_cast<unsigned short*>(&l);
}

// ---------------- convert W_out -> bf16 hi/lo; block 0 also zeros h0/c0 ----------------
__global__ void k_convW(const float* __restrict__ W) {
    int n = blockIdx.x;               // 0..V-1
    int k0 = threadIdx.x * 4;         // 0..1020
    if (n == 0) {
        for (int i = threadIdx.x; i < B * H; i += 256) { g_Hbuf[i] = 0.f; g_cbuf[i] = 0.f; }
    }
    float4 w = *(const float4*)(W + (size_t)n * H + k0);
    unsigned short h0, h1, h2, h3, l0, l1, l2, l3;
    split2(w.x, h0, l0); split2(w.y, h1, l1); split2(w.z, h2, l2); split2(w.w, h3, l3);
    uint2 hv = make_uint2((uint32_t)h0 | ((uint32_t)h1 << 16), (uint32_t)h2 | ((uint32_t)h3 << 16));
    uint2 lv = make_uint2((uint32_t)l0 | ((uint32_t)l1 << 16), (uint32_t)l2 | ((uint32_t)l3 << 16));
    *(uint2*)(g_Whi + ((size_t)n * H + k0) * 2) = hv;
    *(uint2*)(g_Wlo + ((size_t)n * H + k0) * 2) = lv;
}

// ---------------- convert h matrix (row m = t*32+b -> h_{t+1}[b]) ----------------
__global__ void k_convA() {
    int m = blockIdx.x;               // 0..2047
    int k0 = threadIdx.x * 4;
    float4 w = *(const float4*)(g_Hbuf + (size_t)(m + B) * H + k0);
    unsigned short h0, h1, h2, h3, l0, l1, l2, l3;
    split2(w.x, h0, l0); split2(w.y, h1, l1); split2(w.z, h2, l2); split2(w.w, h3, l3);
    uint2 hv = make_uint2((uint32_t)h0 | ((uint32_t)h1 << 16), (uint32_t)h2 | ((uint32_t)h3 << 16));
    uint2 lv = make_uint2((uint32_t)l0 | ((uint32_t)l1 << 16), (uint32_t)l2 | ((uint32_t)l3 << 16));
    *(uint2*)(g_Ahi + ((size_t)m * H + k0) * 2) = hv;
    *(uint2*)(g_Alo + ((size_t)m * H + k0) * 2) = lv;
}

// ---------------- mma / ldmatrix helpers ----------------
__device__ __forceinline__ void mma16816(float* d, const uint32_t* a, const uint32_t* b) {
    asm volatile(
        "mma.sync.aligned.m16n8k16.row.col.f32.bf16.bf16.f32 "
        "{%0,%1,%2,%3}, {%4,%5,%6,%7}, {%8,%9}, {%0,%1,%2,%3};"
        : "+f"(d[0]), "+f"(d[1]), "+f"(d[2]), "+f"(d[3])
        : "r"(a[0]), "r"(a[1]), "r"(a[2]), "r"(a[3]), "r"(b[0]), "r"(b[1]));
}

__device__ __forceinline__ void ldsm_x4(uint32_t* r, uint32_t a) {
    asm volatile("ldmatrix.sync.aligned.m8n8.x4.shared.b16 {%0,%1,%2,%3}, [%4];"
                 : "=r"(r[0]), "=r"(r[1]), "=r"(r[2]), "=r"(r[3]) : "r"(a));
}
__device__ __forceinline__ void ldsm_x2(uint32_t* r, uint32_t a) {
    asm volatile("ldmatrix.sync.aligned.m8n8.x2.shared.b16 {%0,%1}, [%2];"
                 : "=r"(r[0]), "=r"(r[1]) : "r"(a));
}

__device__ __forceinline__ uint32_t smem_u32(const void* p) {
    uint32_t a;
    asm("{ .reg .u64 t; cvta.to.shared.u64 t, %1; cvt.u32.u64 %0, t; }" : "=r"(a) : "l"(p));
    return a;
}

__device__ __forceinline__ void cp16(void* dst_smem, const void* src_gmem) {
    uint32_t d;
    asm("{ .reg .u64 t; cvta.to.shared.u64 t, %1; cvt.u32.u64 %0, t; }" : "=r"(d) : "l"(dst_smem));
    asm volatile("cp.async.ca.shared.global [%0], [%1], 16;" :: "r"(d), "l"(src_gmem) : "memory");
}

// ---------------- tensor-core vocab GEMM (2 CTAs/SM) ----------------
__global__ __launch_bounds__(256, 2) void k_mma2(const float* __restrict__ bout,
                                                 float* __restrict__ out) {
    extern __shared__ __align__(16) unsigned char sm[];
    const uint32_t sbase = smem_u32(sm);
    const int tid = threadIdx.x;
    const int wid = tid >> 5, lane = tid & 31;
    const int gid = lane >> 2, tig = lane & 3;
    const int wm = wid >> 2, wn = wid & 3;           // 2 x 4 warp grid
    const int mt = blockIdx.x, nt = blockIdx.y;

    const size_t aRow0 = (size_t)mt * TM;
    const size_t bRow0 = (size_t)nt * TN;

    const uint32_t aLaneRow = (uint32_t)((lane & 7) + ((lane >> 3) & 1) * 8);
    const uint32_t aLaneCol = (uint32_t)((lane >> 4) * 16);
    const uint32_t bLaneRow = (uint32_t)(lane & 7);
    const uint32_t bLaneCol = (uint32_t)(((lane >> 3) & 1) * 16);

    float acc[4][4][4];
#pragma unroll
    for (int i = 0; i < 4; i++)
#pragma unroll
        for (int j = 0; j < 4; j++)
#pragma unroll
            for (int q = 0; q < 4; q++) acc[i][j][q] = 0.f;

    auto load_chunk = [&](int kc, int buf) {
        unsigned char* base = sm + buf * BUF_SM;
        const int kOff = kc * KC;
#pragma unroll
        for (int half = 0; half < 2; half++) {
            int idx = tid + half * 256;              // 0..511
            int row = idx >> 2, quad = idx & 3;
            size_t gA = ((aRow0 + row) * (size_t)H + kOff + quad * 8) * 2;
            size_t gB = ((bRow0 + row) * (size_t)H + kOff + quad * 8) * 2;
            uint32_t so = row * ROWB + quad * 16;
            cp16(base + so,               g_Ahi + gA);
            cp16(base + TILE_SM + so,     g_Alo + gA);
            cp16(base + 2 * TILE_SM + so, g_Whi + gB);
            cp16(base + 3 * TILE_SM + so, g_Wlo + gB);
        }
        asm volatile("cp.async.commit_group;" ::: "memory");
    };

    load_chunk(0, 0);

    for (int kc = 0; kc < NKC; kc++) {
        const int cur = kc & 1;
        if (kc + 1 < NKC) {
            load_chunk(kc + 1, cur ^ 1);
            asm volatile("cp.async.wait_group 1;" ::: "memory");
        } else {
            asm volatile("cp.async.wait_group 0;" ::: "memory");
        }
        __syncthreads();

        const uint32_t base = sbase + cur * BUF_SM;
#pragma unroll
        for (int ks = 0; ks < 2; ks++) {
            const uint32_t kb = (uint32_t)(ks * 32);     // byte offset of k-step
            // Load ALL A fragments for this ks (32 regs live)
            uint32_t ah[4][4], al[4][4];
#pragma unroll
            for (int mi = 0; mi < 4; mi++) {
                uint32_t r = (uint32_t)(wm * 64 + mi * 16) + aLaneRow;
                uint32_t a = base + r * ROWB + kb + aLaneCol;
                ldsm_x4(ah[mi], a);
                ldsm_x4(al[mi], a + TILE_SM);
            }
            // B fragments loaded just-in-time per ni (only 4 regs live)
#pragma unroll
            for (int ni = 0; ni < 4; ni++) {
                uint32_t r = (uint32_t)(wn * 32 + ni * 8) + bLaneRow;
                uint32_t a = base + 2 * TILE_SM + r * ROWB + kb + bLaneCol;
                uint32_t bh[2], bl[2];
                ldsm_x2(bh, a);
                ldsm_x2(bl, a + TILE_SM);
#pragma unroll
                for (int mi = 0; mi < 4; mi++) {
                    mma16816(acc[mi][ni], ah[mi], bh);
                    mma16816(acc[mi][ni], ah[mi], bl);
                    mma16816(acc[mi][ni], al[mi], bh);
                }
            }
        }
        __syncthreads();
    }

#pragma unroll
    for (int mi = 0; mi < 4; mi++) {
#pragma unroll
        for (int half = 0; half < 2; half++) {
            int m = mt * TM + wm * 64 + mi * 16 + gid + half * 8;
            int tt = m >> 5, bb = m & 31;
            float* orow = out + (size_t)bb * ((size_t)T * V) + (size_t)tt * V;
#pragma unroll
            for (int ni = 0; ni < 4; ni++) {
                int v = nt * TN + wn * 32 + ni * 8 + 2 * tig;
                float2 bo = *(const float2*)(bout + v);
                float2 o;
                o.x = acc[mi][ni][half * 2 + 0] + bo.x;
                o.y = acc[mi][ni][half * 2 + 1] + bo.y;
                *(float2*)(orow + v) = o;
            }
        }
    }
}

// ---------------- fp32 SGEMM: xW precompute ----------------
__global__ __launch_bounds__(256, 2) void sgemm_xw(
    const float* __restrict__ Aext, const float* __restrict__ Bw,
    const float* __restrict__ bias1, const float* __restrict__ bias2,
    const int* __restrict__ caps)
{
    __shared__ float As[8][128];
    __shared__ float Bs[8][128];

    const int tid = threadIdx.x;
    const int bx = blockIdx.x, by = blockIdx.y;
    const int tx = tid & 15, ty = tid >> 4;
    const int ldRow = tid >> 1;
    const int ldCol = (tid & 1) * 4;

    const int gRowA = by * 128 + ldRow;
    const float* aptr;
    {
        int b = gRowA & 31, t = gRowA >> 5;
        int token = caps[b * T + t];
        aptr = Aext + (size_t)token * H + ldCol;
    }
    const int gRowB = bx * 128 + ldRow;
    const float* bptr = Bw + (size_t)gRowB * (2 * H) + ldCol;   // x-part: cols [0, H)

    float acc[8][8];
#pragma unroll
    for (int i = 0; i < 8; i++)
#pragma unroll
        for (int j = 0; j < 8; j++) acc[i][j] = 0.f;

    float4 av = *(const float4*)(aptr);
    float4 bv = *(const float4*)(bptr);

    for (int k0 = 0; k0 < H; k0 += 8) {
        As[ldCol + 0][ldRow] = av.x; As[ldCol + 1][ldRow] = av.y;
        As[ldCol + 2][ldRow] = av.z; As[ldCol + 3][ldRow] = av.w;
        Bs[ldCol + 0][ldRow] = bv.x; Bs[ldCol + 1][ldRow] = bv.y;
        Bs[ldCol + 2][ldRow] = bv.z; Bs[ldCol + 3][ldRow] = bv.w;
        __syncthreads();
        if (k0 + 8 < H) {
            av = *(const float4*)(aptr + k0 + 8);
            bv = *(const float4*)(bptr + k0 + 8);
        }
#pragma unroll
        for (int kk = 0; kk < 8; kk++) {
            float4 a0 = *(const float4*)&As[kk][ty * 8];
            float4 a1 = *(const float4*)&As[kk][ty * 8 + 4];
            float4 b0 = *(const float4*)&Bs[kk][tx * 8];
            float4 b1 = *(const float4*)&Bs[kk][tx * 8 + 4];
            float a[8] = {a0.x, a0.y, a0.z, a0.w, a1.x, a1.y, a1.z, a1.w};
            float bb[8] = {b0.x, b0.y, b0.z, b0.w, b1.x, b1.y, b1.z, b1.w};
#pragma unroll
            for (int i = 0; i < 8; i++)
#pragma unroll
                for (int j = 0; j < 8; j++) acc[i][j] += a[i] * bb[j];
        }
        __syncthreads();
    }

#pragma unroll
    for (int i = 0; i < 8; i++) {
        int m = by * 128 + ty * 8 + i;
#pragma unroll
        for (int j = 0; j < 8; j += 4) {
            int n = bx * 128 + tx * 8 + j;
            float4 o;
            o.x = acc[i][j + 0] + bias1[n + 0] + bias2[n + 0];
            o.y = acc[i][j + 1] + bias1[n + 1] + bias2[n + 1];
            o.z = acc[i][j + 2] + bias1[n + 2] + bias2[n + 2];
            o.w = acc[i][j + 3] + bias1[n + 3] + bias2[n + 3];
            *(float4*)&g_xW[(size_t)m * G4 + n] = o;
        }
    }
}

// ---------------- fp32 SGEMM: M2 = memory @ attn_W ----------------
__global__ __launch_bounds__(256, 2) void sgemm_M2(
    const float* __restrict__ mem, const float* __restrict__ attnW)
{
    __shared__ float As[8][128];
    __shared__ float Bs[8][128];

    const int tid = threadIdx.x;
    const int bx = blockIdx.x, by = blockIdx.y;
    const int tx = tid & 15, ty = tid >> 4;

    const int ldRow = tid >> 1;
    const int ldCol = (tid & 1) * 4;
    const float* aptr = mem + (size_t)(by * 128 + ldRow) * H + ldCol;

    const int bkk = tid >> 5;
    const int bj4 = (tid & 31) * 4;
    const float* bptr = attnW + (size_t)bkk * H + bx * 128 + bj4;

    float acc[8][8];
#pragma unroll
    for (int i = 0; i < 8; i++)
#pragma unroll
        for (int j = 0; j < 8; j++) acc[i][j] = 0.f;

    float4 av = *(const float4*)(aptr);
    float4 bv = *(const float4*)(bptr);

    for (int k0 = 0; k0 < H; k0 += 8) {
        As[ldCol + 0][ldRow] = av.x; As[ldCol + 1][ldRow] = av.y;
        As[ldCol + 2][ldRow] = av.z; As[ldCol + 3][ldRow] = av.w;
        *(float4*)&Bs[bkk][bj4] = bv;
        __syncthreads();
        if (k0 + 8 < H) {
            av = *(const float4*)(aptr + k0 + 8);
            bv = *(const float4*)(bptr + (size_t)(k0 + 8) * H);
        }
#pragma unroll
        for (int kk = 0; kk < 8; kk++) {
            float4 a0 = *(const float4*)&As[kk][ty * 8];
            float4 a1 = *(const float4*)&As[kk][ty * 8 + 4];
            float4 b0 = *(const float4*)&Bs[kk][tx * 8];
            float4 b1 = *(const float4*)&Bs[kk][tx * 8 + 4];
            float a[8] = {a0.x, a0.y, a0.z, a0.w, a1.x, a1.y, a1.z, a1.w};
            float bb[8] = {b0.x, b0.y, b0.z, b0.w, b1.x, b1.y, b1.z, b1.w};
#pragma unroll
            for (int i = 0; i < 8; i++)
#pragma unroll
                for (int j = 0; j < 8; j++) acc[i][j] += a[i] * bb[j];
        }
        __syncthreads();
    }

#pragma unroll
    for (int i = 0; i < 8; i++) {
        int r = by * 128 + ty * 8 + i;
#pragma unroll
        for (int j = 0; j < 8; j += 4) {
            int n = bx * 128 + tx * 8 + j;
            float4 o = make_float4(acc[i][j], acc[i][j + 1], acc[i][j + 2], acc[i][j + 3]);
            *(float4*)&g_M2[(size_t)r * H + n] = o;
        }
    }
}

// ---------------- scores: one warp per s (grid 49 x B, 128 thr) ----------------
__global__ __launch_bounds__(128) void k_score(int t)
{
    __shared__ float sHv[H];
    const int b = blockIdx.y;
    const int tid = threadIdx.x;
    const int warp = tid >> 5, lane = tid & 31;
    const int s = blockIdx.x * 4 + warp;             // 49*4 = 196 exactly

    const float* hrow = g_Hbuf + (size_t)t * B * H + (size_t)b * H;
    for (int i = tid * 4; i < H; i += 128 * 4)
        *(float4*)&sHv[i] = *(const float4*)(hrow + i);
    __syncthreads();

    const float* mrow = g_M2 + ((size_t)b * S + s) * H;
    float acc = 0.f;
#pragma unroll
    for (int i = 0; i < 8; i++) {
        int k = i * 128 + lane * 4;
        float4 m4 = *(const float4*)(mrow + k);
        float4 q4 = *(const float4*)&sHv[k];
        acc += m4.x * q4.x + m4.y * q4.y + m4.z * q4.z + m4.w * q4.w;
    }
#pragma unroll
    for (int o = 16; o > 0; o >>= 1) acc += __shfl_down_sync(0xffffffffu, acc, o);
    if (lane == 0) g_scores[b * S + s] = acc;
}

// ---------------- softmax + ctx ----------------
__global__ __launch_bounds__(256) void k_softctx(const float* __restrict__ mem)
{
    __shared__ float sw_[S];
    __shared__ float red[8];
    const int b = blockIdx.y;
    const int tid = threadIdx.x;
    const int warp = tid >> 5, lane = tid & 31;

    float v = (tid < S) ? g_scores[b * S + tid] : -1e30f;
    float m = v;
#pragma unroll
    for (int o = 16; o > 0; o >>= 1) m = fmaxf(m, __shfl_xor_sync(0xffffffffu, m, o));
    if (lane == 0) red[warp] = m;
    __syncthreads();
    float bm = red[0];
#pragma unroll
    for (int w = 1; w < 8; w++) bm = fmaxf(bm, red[w]);
    float e = (tid < S) ? expf(v - bm) : 0.f;
    __syncthreads();
    float sacc = e;
#pragma unroll
    for (int o = 16; o > 0; o >>= 1) sacc += __shfl_xor_sync(0xffffffffu, sacc, o);
    if (lane == 0) red[warp] = sacc;
    __syncthreads();
    float total = 0.f;
#pragma unroll
    for (int w = 0; w < 8; w++) total += red[w];
    if (tid < S) sw_[tid] = e / total;
    __syncthreads();

    int h = blockIdx.x * 256 + tid;       // gridDim.x = 4
    const float* mb = mem + (size_t)b * S * H + h;
    // dual accumulators (even/odd s) to double load-level parallelism
    float acc0 = 0.f, acc1 = 0.f;
#pragma unroll 7
    for (int s2 = 0; s2 < S; s2 += 2) {
        acc0 += sw_[s2] * mb[(size_t)s2 * H];
        acc1 += sw_[s2 + 1] * mb[(size_t)(s2 + 1) * H];
    }
    g_ctx[b * H + h] = acc0 + acc1;
}

// ---------------- gates + LSTM pointwise ----------------
__global__ __launch_bounds__(256) void k_gates(const float* __restrict__ W_ih,
                                               const float* __restrict__ W_hh, int t)
{
    __shared__ float sA[32][68];
    __shared__ float sW[32][68];
    const int tid = threadIdx.x;
    const int j0 = blockIdx.x * 8;
    const int b = tid >> 3, ji = tid & 7;
    float acc[4] = {0.f, 0.f, 0.f, 0.f};
    const float* hprev = g_Hbuf + (size_t)t * B * H;

    for (int src = 0; src < 2; src++) {
        const float* Ain = (src == 0) ? g_ctx : hprev;
        const float* Wbase = (src == 0) ? W_ih : W_hh;
        const int ldw = (src == 0) ? 2 * H : H;
        const int off = (src == 0) ? H : 0;
        for (int k0 = 0; k0 < H; k0 += 64) {
            __syncthreads();
            {
                int row = tid >> 3;
                int kk = (tid & 7) * 8;
                const float* p = Ain + row * H + k0 + kk;
                *(float4*)&sA[row][kk] = *(const float4*)p;
                *(float4*)&sA[row][kk + 4] = *(const float4*)(p + 4);
                int n = (row >> 3) * H + j0 + (row & 7);
                const float* wp = Wbase + (size_t)n * ldw + off + k0 + kk;
                *(float4*)&sW[row][kk] = *(const float4*)wp;
                *(float4*)&sW[row][kk + 4] = *(const float4*)(wp + 4);
            }
            __syncthreads();
#pragma unroll
            for (int kk = 0; kk < 64; kk += 4) {
                float4 a = *(const float4*)&sA[b][kk];
#pragma unroll
                for (int g = 0; g < 4; g++) {
                    float4 w = *(const float4*)&sW[g * 8 + ji][kk];
                    acc[g] += a.x * w.x + a.y * w.y + a.z * w.z + a.w * w.w;
                }
            }
        }
    }

    const int j = j0 + ji;
    const size_t xbase = ((size_t)t * B + b) * G4 + j;
    float gi = acc[0] + g_xW[xbase];
    float gf = acc[1] + g_xW[xbase + H];
    float gg = acc[2] + g_xW[xbase + 2 * H];
    float go = acc[3] + g_xW[xbase + 3 * H];
    gi = 1.f / (1.f + expf(-gi));
    gf = 1.f / (1.f + expf(-gf));
    gg = tanhf(gg);
    go = 1.f / (1.f + expf(-go));
    float c_old = g_cbuf[(t & 1) * B * H + b * H + j];
    float c_new = gf * c_old + gi * gg;
    float h_new = go * tanhf(c_new);
    g_cbuf[((t + 1) & 1) * B * H + b * H + j] = c_new;
    g_Hbuf[(size_t)(t + 1) * B * H + b * H + j] = h_new;
}

// ---------------- tail: final h, c ----------------
__global__ void k_tail(float* __restrict__ out)
{
    int i = blockIdx.x * blockDim.x + threadIdx.x;
    if (i < B * H) {
        out[(size_t)B * T * V + i] = g_Hbuf[(size_t)T * B * H + i];
        out[(size_t)B * T * V + B * H + i] = g_cbuf[0 * B * H + i];
    }
}

// ---------------- launch ----------------
extern "C" void kernel_launch(void* const* d_in, const int* in_sizes, int n_in,
                              void* d_out, int out_size)
{
    const float* memory   = (const float*)d_in[0];
    const int*   captions = (const int*)d_in[1];
    const float* emb      = (const float*)d_in[2];
    const float* attnW    = (const float*)d_in[3];
    const float* W_ih     = (const float*)d_in[4];
    const float* W_hh     = (const float*)d_in[5];
    const float* b_ih     = (const float*)d_in[6];
    const float* b_hh     = (const float*)d_in[7];
    const float* W_out    = (const float*)d_in[8];
    const float* b_out    = (const float*)d_in[9];
    float* out = (float*)d_out;

    cudaFuncSetAttribute(k_mma2, cudaFuncAttributeMaxDynamicSharedMemorySize, SMEM_MMA);

    k_convW<<<V, 256>>>(W_out);

    {
        dim3 g(G4 / 128, (T * B) / 128);   // (32, 16)
        sgemm_xw<<<g, 256>>>(emb, W_ih, b_ih, b_hh, captions);
    }

    {
        dim3 g(H / 128, (B * S) / 128);    // (8, 49)
        sgemm_M2<<<g, 256>>>(memory, attnW);
    }

    for (int t = 0; t < T; t++) {
        k_score<<<dim3(49, B), 128>>>(t);
        k_softctx<<<dim3(4, B), 256>>>(memory);
        k_gates<<<128, 256>>>(W_ih, W_hh, t);
    }

    k_convA<<<T * B, 256>>>();
    {
        dim3 g(T * B / TM, V / TN);        // (16, 250): m fastest for W-tile L2 reuse
        k_mma2<<<g, 256, SMEM_MMA>>>(b_out, out);
    }

    k_tail<<<(B * H + 255) / 256, 256>>>(out);
}